// round 2
// baseline (speedup 1.0000x reference)
#include <cuda_runtime.h>
#include <cstdint>

typedef unsigned long long ull;

// ---------------------------------------------------------------------------
// Packed f32x2 helpers (Blackwell FFMA2 — only reachable via PTX)
// ---------------------------------------------------------------------------
__device__ __forceinline__ void fma2(ull& d, ull a, ull b) {
    asm("fma.rn.f32x2 %0, %1, %2, %3;" : "=l"(d) : "l"(a), "l"(b), "l"(d));
}
__device__ __forceinline__ ull pack2(float v) {
    ull r;
    unsigned u = __float_as_uint(v);
    asm("mov.b64 %0, {%1, %1};" : "=l"(r) : "r"(u));
    return r;
}
__device__ __forceinline__ void unpack2(ull p, float& lo, float& hi) {
    unsigned a, b;
    asm("mov.b64 {%0, %1}, %2;" : "=r"(a), "=r"(b) : "l"(p));
    lo = __uint_as_float(a);
    hi = __uint_as_float(b);
}

// ---------------------------------------------------------------------------
// Scratch (no allocations allowed -> __device__ globals)
// partial sums per stage: ntiles * B * 128  (stages 1..4 only)
//   stage tiles: 128, 32, 8, 2  -> 262144 + 65536 + 16384 + 4096 = 348160
// ---------------------------------------------------------------------------
__device__ float g_psum[348160];
__device__ float g_psq[348160];
__device__ float g_mean[4 * 2048];
__device__ float g_rstd[4 * 2048];

// ---------------------------------------------------------------------------
// GEMM:  Y[b] (128 x HW) = W[b] (128 x 128) * X[b] (128 x HW)
// Block: one batch b, BN output columns, all 128 output rows.
// Threads: 256.  Thread tile: TM rows x TN(=8) cols, accumulated as f32x2
// pairs over adjacent columns.
// Fused deterministic per-block stats (sum, sumsq per output row).
// ---------------------------------------------------------------------------
template <int BN, bool DO_STATS>
__global__ void __launch_bounds__(256, 2)
gemm_stage_kernel(const float* __restrict__ X, const float* __restrict__ W,
                  float* __restrict__ Y, int HW,
                  int partial_off, int ntiles)
{
    constexpr int BK  = 16;
    constexpr int TN  = 8;
    constexpr int TCG = BN / TN;        // col groups: 16 (BN=128) or 8 (BN=64)
    constexpr int TOG = 256 / TCG;      // row groups: 16 or 32
    constexpr int TM  = 128 / TOG;      // rows per thread: 8 or 4

    // smem: W chunk (transposed) + X chunk; reused for the stats reduction
    constexpr int SM_FLOATS = BK * 128 + BK * BN;
    __shared__ __align__(16) float smem[SM_FLOATS];
    float* Wt = smem;             // [BK][128]  Wt[k][o]
    float* Xs = smem + BK * 128;  // [BK][BN]   Xs[k][p]

    const int b    = blockIdx.y;
    const int tile = blockIdx.x;
    const int p0   = tile * BN;
    const int tid  = threadIdx.x;
    const int cg   = tid % TCG;
    const int og   = tid / TCG;
    const int orow = og * TM;
    const int pcol = cg * TN;

    const float* Xb = X + (size_t)b * 128 * HW;
    const float* Wb = W + (size_t)b * 128 * 128;

    ull acc[TM][TN / 2];
    #pragma unroll
    for (int m = 0; m < TM; ++m)
        #pragma unroll
        for (int n = 0; n < TN / 2; ++n) acc[m][n] = 0ull;

    for (int kk = 0; kk < 128; kk += BK) {
        // --- load W chunk transposed: Wt[k][o] = Wb[o*128 + kk + k]
        #pragma unroll
        for (int j = 0; j < (BK * 128 / 4) / 256; ++j) {
            int i = tid + j * 256;          // over 512 float4
            int o = i >> 2;
            int q = (i & 3) * 4;            // k offset within chunk
            float4 v = *(const float4*)(Wb + o * 128 + kk + q);
            Wt[(q + 0) * 128 + o] = v.x;
            Wt[(q + 1) * 128 + o] = v.y;
            Wt[(q + 2) * 128 + o] = v.z;
            Wt[(q + 3) * 128 + o] = v.w;
        }
        // --- load X chunk: Xs[k][p] = Xb[(kk+k)*HW + p0 + p]
        constexpr int XV = BK * BN / 4;
        #pragma unroll
        for (int j = 0; j < XV / 256; ++j) {
            int i = tid + j * 256;
            int k  = i / (BN / 4);
            int p4 = i % (BN / 4);
            *(float4*)(Xs + k * BN + p4 * 4) =
                *(const float4*)(Xb + (size_t)(kk + k) * HW + p0 + p4 * 4);
        }
        __syncthreads();

        #pragma unroll
        for (int k = 0; k < BK; ++k) {
            float a[TM];
            #pragma unroll
            for (int m4 = 0; m4 < TM; m4 += 4) {
                float4 v = *(const float4*)(Wt + k * 128 + orow + m4);
                a[m4 + 0] = v.x; a[m4 + 1] = v.y;
                a[m4 + 2] = v.z; a[m4 + 3] = v.w;
            }
            ull b2[TN / 2];
            const ull* xr = (const ull*)(Xs + k * BN + pcol);
            #pragma unroll
            for (int n = 0; n < TN / 2; ++n) b2[n] = xr[n];
            #pragma unroll
            for (int m = 0; m < TM; ++m) {
                ull a2 = pack2(a[m]);
                #pragma unroll
                for (int n = 0; n < TN / 2; ++n) fma2(acc[m][n], a2, b2[n]);
            }
        }
        __syncthreads();
    }

    // --- epilogue: write Y, accumulate local stats
    float* Yb = Y + (size_t)b * 128 * HW + p0;
    float lsum[TM], lsq[TM];
    #pragma unroll
    for (int m = 0; m < TM; ++m) {
        float f[TN];
        #pragma unroll
        for (int n = 0; n < TN / 2; ++n) unpack2(acc[m][n], f[2 * n], f[2 * n + 1]);
        float4 v0 = make_float4(f[0], f[1], f[2], f[3]);
        float4 v1 = make_float4(f[4], f[5], f[6], f[7]);
        float* yrow = Yb + (size_t)(orow + m) * HW + pcol;
        *(float4*)(yrow)     = v0;
        *(float4*)(yrow + 4) = v1;
        if (DO_STATS) {
            float s = 0.f, q = 0.f;
            #pragma unroll
            for (int n = 0; n < TN; ++n) { s += f[n]; q += f[n] * f[n]; }
            lsum[m] = s; lsq[m] = q;
        }
    }

    if (DO_STATS) {
        // deterministic block reduction over col-groups, reusing smem
        float* S = smem;               // [TCG][128]
        float* Q = smem + TCG * 128;   // [TCG][128]
        #pragma unroll
        for (int m = 0; m < TM; ++m) {
            S[cg * 128 + orow + m] = lsum[m];
            Q[cg * 128 + orow + m] = lsq[m];
        }
        __syncthreads();
        if (tid < 128) {
            float s = 0.f, q = 0.f;
            #pragma unroll 4
            for (int c = 0; c < TCG; ++c) {
                s += S[c * 128 + tid];
                q += Q[c * 128 + tid];
            }
            size_t idx = (size_t)partial_off + ((size_t)b * ntiles + tile) * 128 + tid;
            g_psum[idx] = s;
            g_psq[idx]  = q;
        }
    }
}

// ---------------------------------------------------------------------------
// finalize: per (b,o) mean & rstd  (2048 channels per stage)
// ---------------------------------------------------------------------------
__global__ void finalize_kernel(int partial_off, int ntiles, float invHW, int stats_off)
{
    int idx = blockIdx.x * blockDim.x + threadIdx.x;
    if (idx >= 2048) return;
    int b = idx >> 7, o = idx & 127;
    float s = 0.f, q = 0.f;
    for (int t = 0; t < ntiles; ++t) {
        size_t j = (size_t)partial_off + ((size_t)b * ntiles + t) * 128 + o;
        s += g_psum[j];
        q += g_psq[j];
    }
    float m = s * invHW;
    float v = fmaf(q, invHW, -m * m);
    g_mean[stats_off + idx] = m;
    g_rstd[stats_off + idx] = rsqrtf(v + 1e-5f);
}

// ---------------------------------------------------------------------------
// normalize: y = (y - mean) * rstd   (vectorized float4)
// ---------------------------------------------------------------------------
__global__ void norm_kernel(float* __restrict__ Y, int stats_off, int shift, int total4)
{
    int i = blockIdx.x * blockDim.x + threadIdx.x;
    if (i >= total4) return;
    int ch = i >> shift;                 // b*128 + o
    float m = g_mean[stats_off + ch];
    float r = g_rstd[stats_off + ch];
    float4 v = ((float4*)Y)[i];
    v.x = (v.x - m) * r;
    v.y = (v.y - m) * r;
    v.z = (v.z - m) * r;
    v.w = (v.w - m) * r;
    ((float4*)Y)[i] = v;
}

// ---------------------------------------------------------------------------
// launch
// ---------------------------------------------------------------------------
extern "C" void kernel_launch(void* const* d_in, const int* in_sizes, int n_in,
                              void* d_out, int out_size)
{
    // Identify inputs by element count (robust to interleaved or grouped order;
    // the five weight tensors share a size and appear in stage order).
    const float* xs[5] = {nullptr, nullptr, nullptr, nullptr, nullptr};
    const float* ws[5] = {nullptr, nullptr, nullptr, nullptr, nullptr};
    int wcount = 0;
    for (int i = 0; i < n_in; ++i) {
        const float* p = (const float*)d_in[i];
        switch (in_sizes[i]) {
            case 33554432: xs[0] = p; break;   // x1: 16*128*128*128
            case 8388608:  xs[1] = p; break;   // x2
            case 2097152:  xs[2] = p; break;   // x3
            case 524288:   xs[3] = p; break;   // x4
            case 131072:   xs[4] = p; break;   // x5
            case 262144:   if (wcount < 5) ws[wcount++] = p; break; // l{i}fs
            default: break;
        }
    }

    float* out = (float*)d_out;
    const int    HWs[5]    = {16384, 4096, 1024, 256, 64};
    const int    ntiles[5] = {128, 32, 8, 2, 1};
    const size_t yoff[5]   = {0, 33554432, 41943040, 44040192, 44564480};
    const int    poff[4]   = {0, 262144, 327680, 344064};

    // stages 1..4: BN=128, fused stats
    for (int s = 0; s < 4; ++s) {
        dim3 grid(ntiles[s], 16);
        gemm_stage_kernel<128, true><<<grid, 256>>>(
            xs[s], ws[s], out + yoff[s], HWs[s], poff[s], ntiles[s]);
    }
    // stage 5: BN=64, no norm
    {
        dim3 grid(1, 16);
        gemm_stage_kernel<64, false><<<grid, 256>>>(
            xs[4], ws[4], out + yoff[4], HWs[4], 0, 1);
    }

    // finalize stats
    for (int s = 0; s < 4; ++s) {
        finalize_kernel<<<8, 256>>>(poff[s], ntiles[s], 1.0f / HWs[s], s * 2048);
    }

    // normalize stages 1..4
    for (int s = 0; s < 4; ++s) {
        int total4 = 16 * 128 * HWs[s] / 4;
        int shift  = (s == 0) ? 12 : (s == 1) ? 10 : (s == 2) ? 8 : 6;
        int blocks = (total4 + 255) / 256;
        norm_kernel<<<blocks, 256>>>(out + yoff[s], s * 2048, shift, total4);
    }

    (void)out_size;
}

// round 3
// speedup vs baseline: 1.2694x; 1.2694x over previous
#include <cuda_runtime.h>
#include <cstdint>

typedef unsigned long long ull;

// ---------------------------------------------------------------------------
// Packed f32x2 helpers (Blackwell FFMA2 — only reachable via PTX)
// ---------------------------------------------------------------------------
__device__ __forceinline__ void fma2(ull& d, ull a, ull b) {
    asm("fma.rn.f32x2 %0, %1, %2, %3;" : "=l"(d) : "l"(a), "l"(b), "l"(d));
}
__device__ __forceinline__ ull pack2(float v) {
    ull r;
    unsigned u = __float_as_uint(v);
    asm("mov.b64 %0, {%1, %1};" : "=l"(r) : "r"(u));
    return r;
}
__device__ __forceinline__ void unpack2(ull p, float& lo, float& hi) {
    unsigned a, b;
    asm("mov.b64 {%0, %1}, %2;" : "=r"(a), "=r"(b) : "l"(p));
    lo = __uint_as_float(a);
    hi = __uint_as_float(b);
}

// ---------------------------------------------------------------------------
// Scratch (no allocations allowed -> __device__ globals)
// partial sums per stage: ntiles * B * 128  (stages 1..4 only)
//   stage tiles: 128, 32, 8, 2 -> offsets 0, 262144, 327680, 344064
// ---------------------------------------------------------------------------
__device__ float g_psum[348160];
__device__ float g_psq[348160];

// ---------------------------------------------------------------------------
// GEMM tile:  Y[b] (128 x HW) = W[b] (128 x 128) * X[b] (128 x HW)
// One CTA: batch b, BN output columns, all 128 output rows. 256 threads.
// Thread tile: TM rows x TN(=8) cols as f32x2 pairs over adjacent columns.
// Fused deterministic per-block stats (sum, sumsq per output row).
// ---------------------------------------------------------------------------
template <int BN, bool DO_STATS>
__device__ __forceinline__ void gemm_tile(
    const float* __restrict__ X, const float* __restrict__ W,
    float* __restrict__ Y, int HW, int partial_off, int ntiles,
    int tile, int b, float* smem)
{
    constexpr int BK  = 16;
    constexpr int TN  = 8;
    constexpr int TCG = BN / TN;        // col groups: 16 (BN=128) or 8 (BN=64)
    constexpr int TOG = 256 / TCG;      // row groups: 16 or 32
    constexpr int TM  = 128 / TOG;      // rows per thread: 8 or 4

    float* Wt = smem;             // [BK][128]  Wt[k][o]
    float* Xs = smem + BK * 128;  // [BK][BN]   Xs[k][p]

    const int p0   = tile * BN;
    const int tid  = threadIdx.x;
    const int cg   = tid % TCG;
    const int og   = tid / TCG;
    const int orow = og * TM;
    const int pcol = cg * TN;

    const float* Xb = X + (size_t)b * 128 * HW;
    const float* Wb = W + (size_t)b * 128 * 128;

    ull acc[TM][TN / 2];
    #pragma unroll
    for (int m = 0; m < TM; ++m)
        #pragma unroll
        for (int n = 0; n < TN / 2; ++n) acc[m][n] = 0ull;

    for (int kk = 0; kk < 128; kk += BK) {
        // --- load W chunk transposed: Wt[k][o] = Wb[o*128 + kk + k]
        #pragma unroll
        for (int j = 0; j < (BK * 128 / 4) / 256; ++j) {
            int i = tid + j * 256;          // over 512 float4
            int o = i >> 2;
            int q = (i & 3) * 4;            // k offset within chunk
            float4 v = *(const float4*)(Wb + o * 128 + kk + q);
            Wt[(q + 0) * 128 + o] = v.x;
            Wt[(q + 1) * 128 + o] = v.y;
            Wt[(q + 2) * 128 + o] = v.z;
            Wt[(q + 3) * 128 + o] = v.w;
        }
        // --- load X chunk: Xs[k][p] = Xb[(kk+k)*HW + p0 + p]
        constexpr int XV = BK * BN / 4;
        #pragma unroll
        for (int j = 0; j < XV / 256; ++j) {
            int i = tid + j * 256;
            int k  = i / (BN / 4);
            int p4 = i % (BN / 4);
            *(float4*)(Xs + k * BN + p4 * 4) =
                *(const float4*)(Xb + (size_t)(kk + k) * HW + p0 + p4 * 4);
        }
        __syncthreads();

        #pragma unroll
        for (int k = 0; k < BK; ++k) {
            float a[TM];
            #pragma unroll
            for (int m4 = 0; m4 < TM; m4 += 4) {
                float4 v = *(const float4*)(Wt + k * 128 + orow + m4);
                a[m4 + 0] = v.x; a[m4 + 1] = v.y;
                a[m4 + 2] = v.z; a[m4 + 3] = v.w;
            }
            ull b2[TN / 2];
            const ull* xr = (const ull*)(Xs + k * BN + pcol);
            #pragma unroll
            for (int n = 0; n < TN / 2; ++n) b2[n] = xr[n];
            #pragma unroll
            for (int m = 0; m < TM; ++m) {
                ull a2 = pack2(a[m]);
                #pragma unroll
                for (int n = 0; n < TN / 2; ++n) fma2(acc[m][n], a2, b2[n]);
            }
        }
        __syncthreads();
    }

    // --- epilogue: write Y, accumulate local stats
    float* Yb = Y + (size_t)b * 128 * HW + p0;
    float lsum[TM], lsq[TM];
    #pragma unroll
    for (int m = 0; m < TM; ++m) {
        float f[TN];
        #pragma unroll
        for (int n = 0; n < TN / 2; ++n) unpack2(acc[m][n], f[2 * n], f[2 * n + 1]);
        float4 v0 = make_float4(f[0], f[1], f[2], f[3]);
        float4 v1 = make_float4(f[4], f[5], f[6], f[7]);
        float* yrow = Yb + (size_t)(orow + m) * HW + pcol;
        *(float4*)(yrow)     = v0;
        *(float4*)(yrow + 4) = v1;
        if (DO_STATS) {
            float s = 0.f, q = 0.f;
            #pragma unroll
            for (int n = 0; n < TN; ++n) { s += f[n]; q += f[n] * f[n]; }
            lsum[m] = s; lsq[m] = q;
        }
    }

    if (DO_STATS) {
        // deterministic block reduction over col-groups, reusing smem
        float* S = smem;               // [TCG][128]
        float* Q = smem + TCG * 128;   // [TCG][128]
        #pragma unroll
        for (int m = 0; m < TM; ++m) {
            S[cg * 128 + orow + m] = lsum[m];
            Q[cg * 128 + orow + m] = lsq[m];
        }
        __syncthreads();
        if (tid < 128) {
            float s = 0.f, q = 0.f;
            #pragma unroll 4
            for (int c = 0; c < TCG; ++c) {
                s += S[c * 128 + tid];
                q += Q[c * 128 + tid];
            }
            size_t idx = (size_t)partial_off + ((size_t)b * ntiles + tile) * 128 + tid;
            g_psum[idx] = s;
            g_psq[idx]  = q;
        }
    }
}

// ---------------------------------------------------------------------------
// ONE launch for all five stages. Small stages first in blockIdx order so the
// trailing waves are uniform stage-1 CTAs (no latency-bound tail).
//   [0,16)     stage5  nt=1   BN=64
//   [16,48)    stage4  nt=2
//   [48,176)   stage3  nt=8
//   [176,688)  stage2  nt=32
//   [688,2736) stage1  nt=128
// ---------------------------------------------------------------------------
struct KArgs {
    const float* x[5];
    const float* w[5];
};

__global__ void __launch_bounds__(256, 2)
gemm_all_kernel(KArgs a, float* __restrict__ out)
{
    __shared__ __align__(16) float smem[4096];   // 16 KB, covers both paths
    int bx = blockIdx.x;
    if (bx < 16) {
        gemm_tile<64, false>(a.x[4], a.w[4], out + 44564480, 64, 0, 1,
                             0, bx, smem);
    } else if (bx < 48) {
        int l = bx - 16;
        gemm_tile<128, true>(a.x[3], a.w[3], out + 44040192, 256, 344064, 2,
                             l % 2, l / 2, smem);
    } else if (bx < 176) {
        int l = bx - 48;
        gemm_tile<128, true>(a.x[2], a.w[2], out + 41943040, 1024, 327680, 8,
                             l % 8, l / 8, smem);
    } else if (bx < 688) {
        int l = bx - 176;
        gemm_tile<128, true>(a.x[1], a.w[1], out + 33554432, 4096, 262144, 32,
                             l % 32, l / 32, smem);
    } else {
        int l = bx - 688;
        gemm_tile<128, true>(a.x[0], a.w[0], out, 16384, 0, 128,
                             l % 128, l / 128, smem);
    }
}

// ---------------------------------------------------------------------------
// ONE launch for finalize + normalize of stages 1..4.
// Block = one (stage, b, o) channel: tree-reduce its tile partials in smem
// (fixed order -> deterministic), then normalize HW elements with float4.
// Stage-1 blocks first (largest work first).
//   [0,2048) s1, [2048,4096) s2, [4096,6144) s3, [6144,8192) s4
// ---------------------------------------------------------------------------
__global__ void __launch_bounds__(256)
norm_all_kernel(float* __restrict__ out)
{
    __shared__ float ssum[128], ssq[128];
    __shared__ float s_m, s_r;

    int bx = blockIdx.x;
    int s  = bx >> 11;
    int ch = bx & 2047;

    int ntiles, HW, poff;
    size_t yoff;
    switch (s) {
        case 0:  ntiles = 128; HW = 16384; yoff = 0;        poff = 0;      break;
        case 1:  ntiles = 32;  HW = 4096;  yoff = 33554432; poff = 262144; break;
        case 2:  ntiles = 8;   HW = 1024;  yoff = 41943040; poff = 327680; break;
        default: ntiles = 2;   HW = 256;   yoff = 44040192; poff = 344064; break;
    }
    int b = ch >> 7, o = ch & 127;
    int tid = threadIdx.x;

    if (tid < 128) {
        float sv = 0.f, qv = 0.f;
        if (tid < ntiles) {
            size_t j = (size_t)poff + ((size_t)b * ntiles + tid) * 128 + o;
            sv = g_psum[j];
            qv = g_psq[j];
        }
        ssum[tid] = sv;
        ssq[tid]  = qv;
    }
    __syncthreads();
    #pragma unroll
    for (int off = 64; off > 0; off >>= 1) {
        if (tid < off) {
            ssum[tid] += ssum[tid + off];
            ssq[tid]  += ssq[tid + off];
        }
        __syncthreads();
    }
    if (tid == 0) {
        float inv = 1.0f / (float)HW;
        float m = ssum[0] * inv;
        float v = fmaf(ssq[0], inv, -m * m);
        s_m = m;
        s_r = rsqrtf(v + 1e-5f);
    }
    __syncthreads();

    float m = s_m, r = s_r;
    float4* Yp = (float4*)(out + yoff + (size_t)(b * 128 + o) * HW);
    int n4 = HW >> 2;
    for (int i = tid; i < n4; i += 256) {
        float4 v = Yp[i];
        v.x = (v.x - m) * r;
        v.y = (v.y - m) * r;
        v.z = (v.z - m) * r;
        v.w = (v.w - m) * r;
        Yp[i] = v;
    }
}

// ---------------------------------------------------------------------------
// launch: exactly two kernels
// ---------------------------------------------------------------------------
extern "C" void kernel_launch(void* const* d_in, const int* in_sizes, int n_in,
                              void* d_out, int out_size)
{
    KArgs args{};
    int wcount = 0;
    for (int i = 0; i < n_in; ++i) {
        const float* p = (const float*)d_in[i];
        switch (in_sizes[i]) {
            case 33554432: args.x[0] = p; break;   // x1: 16*128*128*128
            case 8388608:  args.x[1] = p; break;   // x2
            case 2097152:  args.x[2] = p; break;   // x3
            case 524288:   args.x[3] = p; break;   // x4
            case 131072:   args.x[4] = p; break;   // x5
            case 262144:   if (wcount < 5) args.w[wcount++] = p; break; // l{i}fs
            default: break;
        }
    }

    float* out = (float*)d_out;
    gemm_all_kernel<<<2736, 256>>>(args, out);
    norm_all_kernel<<<8192, 256>>>(out);

    (void)out_size;
}

// round 5
// speedup vs baseline: 2.0835x; 1.6414x over previous
#include <cuda_runtime.h>
#include <cstdint>

typedef unsigned long long ull;

// ---------------------------------------------------------------------------
// Packed f32x2 helpers (stage-5 FFMA path)
// ---------------------------------------------------------------------------
__device__ __forceinline__ void fma2(ull& d, ull a, ull b) {
    asm("fma.rn.f32x2 %0, %1, %2, %3;" : "=l"(d) : "l"(a), "l"(b), "l"(d));
}
__device__ __forceinline__ ull pack2(float v) {
    ull r;
    unsigned u = __float_as_uint(v);
    asm("mov.b64 %0, {%1, %1};" : "=l"(r) : "r"(u));
    return r;
}
__device__ __forceinline__ void unpack2(ull p, float& lo, float& hi) {
    unsigned a, b;
    asm("mov.b64 {%0, %1}, %2;" : "=r"(a), "=r"(b) : "l"(p));
    lo = __uint_as_float(a);
    hi = __uint_as_float(b);
}

__device__ __forceinline__ uint32_t smem_u32(const void* p) {
    uint32_t a;
    asm("{ .reg .u64 t; cvta.to.shared.u64 t, %1; cvt.u32.u64 %0, t; }" : "=r"(a) : "l"(p));
    return a;
}
__device__ __forceinline__ uint32_t f2tf32(float f) {
    uint32_t r;
    asm("cvt.rna.tf32.f32 %0, %1;" : "=r"(r) : "f"(f));
    return r;
}
__device__ __forceinline__ void cp16(uint32_t dst, const float* src) {
    size_t g = __cvta_generic_to_global(src);
    asm volatile("cp.async.ca.shared.global [%0], [%1], 16;" :: "r"(dst), "l"(g) : "memory");
}
__device__ __forceinline__ void mma_tf32(float* d, const uint32_t* a, const uint32_t* b) {
    asm volatile(
        "mma.sync.aligned.m16n8k8.row.col.f32.tf32.tf32.f32 "
        "{%0,%1,%2,%3}, {%4,%5,%6,%7}, {%8,%9}, {%0,%1,%2,%3};"
        : "+f"(d[0]), "+f"(d[1]), "+f"(d[2]), "+f"(d[3])
        : "r"(a[0]), "r"(a[1]), "r"(a[2]), "r"(a[3]), "r"(b[0]), "r"(b[1]));
}

// ---------------------------------------------------------------------------
// Scratch
// ---------------------------------------------------------------------------
__device__ float g_psum[348160];
__device__ float g_psq[348160];

// ---------------------------------------------------------------------------
// Stage-5 FFMA2 path (HW=64, BN=64, no stats) — 0.4% of the FLOPs
// ---------------------------------------------------------------------------
__device__ __forceinline__ void gemm_tile_ffma64(
    const float* __restrict__ X, const float* __restrict__ W,
    float* __restrict__ Y, int b, float* smem)
{
    constexpr int BK = 16, BN = 64, TN = 8, HW = 64;
    constexpr int TCG = BN / TN;            // 8
    constexpr int TM  = 128 / (256 / TCG);  // 4

    float* Wt = smem;             // [BK][128]
    float* Xs = smem + BK * 128;  // [BK][BN]

    const int tid  = threadIdx.x;
    const int cg   = tid % TCG;
    const int og   = tid / TCG;
    const int orow = og * TM;
    const int pcol = cg * TN;

    const float* Xb = X + (size_t)b * 128 * HW;
    const float* Wb = W + (size_t)b * 128 * 128;

    ull acc[TM][TN / 2];
    #pragma unroll
    for (int m = 0; m < TM; ++m)
        #pragma unroll
        for (int n = 0; n < TN / 2; ++n) acc[m][n] = 0ull;

    for (int kk = 0; kk < 128; kk += BK) {
        #pragma unroll
        for (int j = 0; j < 2; ++j) {
            int i = tid + j * 256;
            int o = i >> 2;
            int q = (i & 3) * 4;
            float4 v = *(const float4*)(Wb + o * 128 + kk + q);
            Wt[(q + 0) * 128 + o] = v.x;
            Wt[(q + 1) * 128 + o] = v.y;
            Wt[(q + 2) * 128 + o] = v.z;
            Wt[(q + 3) * 128 + o] = v.w;
        }
        {
            int i = tid;
            int k  = i / (BN / 4);
            int p4 = i % (BN / 4);
            *(float4*)(Xs + k * BN + p4 * 4) =
                *(const float4*)(Xb + (size_t)(kk + k) * HW + p4 * 4);
        }
        __syncthreads();

        #pragma unroll
        for (int k = 0; k < BK; ++k) {
            float a[TM];
            float4 v = *(const float4*)(Wt + k * 128 + orow);
            a[0] = v.x; a[1] = v.y; a[2] = v.z; a[3] = v.w;
            ull b2[TN / 2];
            const ull* xr = (const ull*)(Xs + k * BN + pcol);
            #pragma unroll
            for (int n = 0; n < TN / 2; ++n) b2[n] = xr[n];
            #pragma unroll
            for (int m = 0; m < TM; ++m) {
                ull a2 = pack2(a[m]);
                #pragma unroll
                for (int n = 0; n < TN / 2; ++n) fma2(acc[m][n], a2, b2[n]);
            }
        }
        __syncthreads();
    }

    float* Yb = Y + (size_t)b * 128 * HW;
    #pragma unroll
    for (int m = 0; m < TM; ++m) {
        float f[TN];
        #pragma unroll
        for (int n = 0; n < TN / 2; ++n) unpack2(acc[m][n], f[2 * n], f[2 * n + 1]);
        float* yrow = Yb + (size_t)(orow + m) * HW + pcol;
        *(float4*)(yrow)     = make_float4(f[0], f[1], f[2], f[3]);
        *(float4*)(yrow + 4) = make_float4(f[4], f[5], f[6], f[7]);
    }
}

// ---------------------------------------------------------------------------
// mma.sync tf32 tile: D[p=128][o=128] = X^T(tile) * W^T, K=128.
//   smem X chunk [c=32][p=128] pitch 132, W chunk [o=128][c=32] pitch 36.
//   cp.async double-buffered over 4 K-chunks of 32.
//   Warp grid 4(p) x 2(o); warp tile 32p x 64o; m16n8k8 frags.
//   Epilogue: accums -> smem Ds[o][p] pitch 132 -> coalesced STG + stats.
// All fragment LDS patterns are bank-conflict-free by pitch construction:
//   X: (4*ca + p) mod 32 distinct;  W: (4*lr + c) mod 32 distinct.
// ---------------------------------------------------------------------------
__device__ __forceinline__ void gemm_tile_mma(
    const float* __restrict__ X, const float* __restrict__ W,
    float* __restrict__ Y, int HW, int partial_off, int ntiles,
    int tile, int b, float* smem, bool do_stats)
{
    constexpr int XP = 132, WP = 36;
    constexpr int XCHUNK = 32 * XP;          // 4224 floats
    constexpr int WCHUNK = 128 * WP;         // 4608 floats
    constexpr int BUFSZ  = XCHUNK + WCHUNK;  // 8832 floats

    const int tid  = threadIdx.x;
    const int wid  = tid >> 5;
    const int lane = tid & 31;
    const int wr = wid >> 1, wc = wid & 1;
    const int P0 = wr * 32, O0 = wc * 64;

    const float* Xb = X + (size_t)b * 128 * HW + (size_t)tile * 128;
    const float* Wb = W + (size_t)b * 128 * 128;

    // ---- async chunk loader
    auto load_chunk = [&](int kk, int buf) {
        float* Xd = smem + buf * BUFSZ;
        float* Wd = Xd + XCHUNK;
        #pragma unroll
        for (int j = 0; j < 4; ++j) {
            int i = tid + j * 256;          // 1024 16B segs: X chunk
            int c  = i >> 5;
            int s4 = (i & 31) * 4;
            cp16(smem_u32(Xd + c * XP + s4), Xb + (size_t)(kk + c) * HW + s4);
        }
        #pragma unroll
        for (int j = 0; j < 4; ++j) {
            int i = tid + j * 256;          // 1024 16B segs: W chunk
            int o  = i >> 3;
            int s4 = (i & 7) * 4;
            cp16(smem_u32(Wd + o * WP + s4), Wb + o * 128 + kk + s4);
        }
        asm volatile("cp.async.commit_group;" ::: "memory");
    };

    float acc[2][8][4];
    #pragma unroll
    for (int mf = 0; mf < 2; ++mf)
        #pragma unroll
        for (int nf = 0; nf < 8; ++nf)
            #pragma unroll
            for (int r = 0; r < 4; ++r) acc[mf][nf][r] = 0.f;

    load_chunk(0, 0);
    load_chunk(32, 1);

    const int ca = lane & 3;     // quad lane
    const int gr = lane >> 2;    // group row

    #pragma unroll
    for (int c = 0; c < 4; ++c) {
        if (c < 3) asm volatile("cp.async.wait_group 1;" ::: "memory");
        else       asm volatile("cp.async.wait_group 0;" ::: "memory");
        __syncthreads();

        const float* Xs = smem + (c & 1) * BUFSZ;
        const float* Ws = Xs + XCHUNK;

        #pragma unroll
        for (int ks = 0; ks < 4; ++ks) {
            const int kc = ks * 8;
            uint32_t afr[2][4];
            #pragma unroll
            for (int mf = 0; mf < 2; ++mf) {
                int pr = P0 + mf * 16 + gr;
                afr[mf][0] = f2tf32(Xs[(kc + ca) * XP + pr]);
                afr[mf][1] = f2tf32(Xs[(kc + ca) * XP + pr + 8]);
                afr[mf][2] = f2tf32(Xs[(kc + ca + 4) * XP + pr]);
                afr[mf][3] = f2tf32(Xs[(kc + ca + 4) * XP + pr + 8]);
            }
            #pragma unroll
            for (int nf = 0; nf < 8; ++nf) {
                uint32_t bfr[2];
                int orow = O0 + nf * 8 + gr;
                bfr[0] = f2tf32(Ws[orow * WP + kc + ca]);
                bfr[1] = f2tf32(Ws[orow * WP + kc + ca + 4]);
                mma_tf32(acc[0][nf], afr[0], bfr);
                mma_tf32(acc[1][nf], afr[1], bfr);
            }
        }
        __syncthreads();
        if (c < 2) load_chunk((c + 2) * 32, c & 1);
    }

    // ---- epilogue: accums -> Ds[o][p] (pitch XP), reuse smem (post-sync safe)
    float* Ds = smem;
    #pragma unroll
    for (int mf = 0; mf < 2; ++mf)
        #pragma unroll
        for (int nf = 0; nf < 8; ++nf) {
            int p = P0 + mf * 16 + gr;
            int o = O0 + nf * 8 + ca * 2;
            Ds[o * XP + p]           = acc[mf][nf][0];
            Ds[(o + 1) * XP + p]     = acc[mf][nf][1];
            Ds[o * XP + p + 8]       = acc[mf][nf][2];
            Ds[(o + 1) * XP + p + 8] = acc[mf][nf][3];
        }
    __syncthreads();

    {
        int o   = tid >> 1;
        int seg = tid & 1;
        const float* row = Ds + o * XP + seg * 64;
        float* yrow = Y + ((size_t)b * 128 + o) * HW + (size_t)tile * 128 + seg * 64;
        float s = 0.f, q = 0.f;
        #pragma unroll
        for (int j = 0; j < 16; ++j) {
            float4 v = ((const float4*)row)[j];
            ((float4*)yrow)[j] = v;
            s += v.x + v.y + v.z + v.w;
            q += v.x * v.x + v.y * v.y + v.z * v.z + v.w * v.w;
        }
        if (do_stats) {
            s += __shfl_xor_sync(0xFFFFFFFFu, s, 1);
            q += __shfl_xor_sync(0xFFFFFFFFu, q, 1);
            if (seg == 0) {
                size_t idx = (size_t)partial_off + ((size_t)b * ntiles + tile) * 128 + o;
                g_psum[idx] = s;
                g_psq[idx]  = q;
            }
        }
    }
}

// ---------------------------------------------------------------------------
// One launch for all five stages (small stages first).
//   [0,16)     stage5  FFMA (HW=64)
//   [16,48)    stage4  nt=2
//   [48,176)   stage3  nt=8
//   [176,688)  stage2  nt=32
//   [688,2736) stage1  nt=128
// ---------------------------------------------------------------------------
struct KArgs {
    const float* x[5];
    const float* w[5];
};

__global__ void __launch_bounds__(256, 2)
gemm_all_kernel(KArgs a, float* __restrict__ out)
{
    extern __shared__ __align__(16) float dynsmem[];
    int bx = blockIdx.x;
    if (bx < 16) {
        gemm_tile_ffma64(a.x[4], a.w[4], out + 44564480, bx, dynsmem);
    } else if (bx < 48) {
        int l = bx - 16;
        gemm_tile_mma(a.x[3], a.w[3], out + 44040192, 256, 344064, 2,
                      l & 1, l >> 1, dynsmem, true);
    } else if (bx < 176) {
        int l = bx - 48;
        gemm_tile_mma(a.x[2], a.w[2], out + 41943040, 1024, 327680, 8,
                      l & 7, l >> 3, dynsmem, true);
    } else if (bx < 688) {
        int l = bx - 176;
        gemm_tile_mma(a.x[1], a.w[1], out + 33554432, 4096, 262144, 32,
                      l & 31, l >> 5, dynsmem, true);
    } else {
        int l = bx - 688;
        gemm_tile_mma(a.x[0], a.w[0], out, 16384, 0, 128,
                      l & 127, l >> 7, dynsmem, true);
    }
}

// ---------------------------------------------------------------------------
// Finalize + normalize stages 1..4 (memory-bound, near floor — unchanged)
// ---------------------------------------------------------------------------
__global__ void __launch_bounds__(256)
norm_all_kernel(float* __restrict__ out)
{
    __shared__ float ssum[128], ssq[128];
    __shared__ float s_m, s_r;

    int bx = blockIdx.x;
    int s  = bx >> 11;
    int ch = bx & 2047;

    int ntiles, HW, poff;
    size_t yoff;
    switch (s) {
        case 0:  ntiles = 128; HW = 16384; yoff = 0;        poff = 0;      break;
        case 1:  ntiles = 32;  HW = 4096;  yoff = 33554432; poff = 262144; break;
        case 2:  ntiles = 8;   HW = 1024;  yoff = 41943040; poff = 327680; break;
        default: ntiles = 2;   HW = 256;   yoff = 44040192; poff = 344064; break;
    }
    int b = ch >> 7, o = ch & 127;
    int tid = threadIdx.x;

    if (tid < 128) {
        float sv = 0.f, qv = 0.f;
        if (tid < ntiles) {
            size_t j = (size_t)poff + ((size_t)b * ntiles + tid) * 128 + o;
            sv = g_psum[j];
            qv = g_psq[j];
        }
        ssum[tid] = sv;
        ssq[tid]  = qv;
    }
    __syncthreads();
    #pragma unroll
    for (int off = 64; off > 0; off >>= 1) {
        if (tid < off) {
            ssum[tid] += ssum[tid + off];
            ssq[tid]  += ssq[tid + off];
        }
        __syncthreads();
    }
    if (tid == 0) {
        float inv = 1.0f / (float)HW;
        float m = ssum[0] * inv;
        float v = fmaf(ssq[0], inv, -m * m);
        s_m = m;
        s_r = rsqrtf(v + 1e-5f);
    }
    __syncthreads();

    float m = s_m, r = s_r;
    float4* Yp = (float4*)(out + yoff + (size_t)(b * 128 + o) * HW);
    int n4 = HW >> 2;
    for (int i = tid; i < n4; i += 256) {
        float4 v = Yp[i];
        v.x = (v.x - m) * r;
        v.y = (v.y - m) * r;
        v.z = (v.z - m) * r;
        v.w = (v.w - m) * r;
        Yp[i] = v;
    }
}

// ---------------------------------------------------------------------------
// launch: two kernels
// ---------------------------------------------------------------------------
extern "C" void kernel_launch(void* const* d_in, const int* in_sizes, int n_in,
                              void* d_out, int out_size)
{
    KArgs args{};
    int wcount = 0;
    for (int i = 0; i < n_in; ++i) {
        const float* p = (const float*)d_in[i];
        switch (in_sizes[i]) {
            case 33554432: args.x[0] = p; break;   // x1
            case 8388608:  args.x[1] = p; break;   // x2
            case 2097152:  args.x[2] = p; break;   // x3
            case 524288:   args.x[3] = p; break;   // x4
            case 131072:   args.x[4] = p; break;   // x5
            case 262144:   if (wcount < 5) args.w[wcount++] = p; break; // l{i}fs
            default: break;
        }
    }

    // 2 * (32*132 + 128*36) floats = 70656 bytes
    const int SMEM_BYTES = 70656;
    cudaFuncSetAttribute(gemm_all_kernel,
                         cudaFuncAttributeMaxDynamicSharedMemorySize, SMEM_BYTES);

    float* out = (float*)d_out;
    gemm_all_kernel<<<2736, 256, SMEM_BYTES>>>(args, out);
    norm_all_kernel<<<8192, 256>>>(out);

    (void)out_size;
}